// round 17
// baseline (speedup 1.0000x reference)
#include <cuda_runtime.h>
#include <cuda_bf16.h>
#include <cuda_fp16.h>
#include <cstdint>

// Problem constants
#define NNODES 4096       // B*N = 8*512
#define KNBR   16
#define CPOOL  256
#define GDIM   128
#define INDIM  384        // CPOOL + GDIM
#define LDIM   512
#define OUTLD  1920       // 384 + 3*512
#define WSTRIDE (1024 * 512)

// ---------------- device scratch (no allocations allowed) ----------------
__device__ float g_biasL[3 * 1024];
__device__ __align__(16) __half g_D  [NNODES * 1024];
__device__ __align__(16) __half g_X0h[NNODES * INDIM];
__device__ __align__(16) __half g_Xh [NNODES * LDIM];
__device__ __align__(16) __half g_Wh [3 * WSTRIDE];
__device__ __align__(16) __half g_Wl [3 * WSTRIDE];

// ======================= helpers =======================
__device__ __forceinline__ uint32_t smem_u32(const void* p) {
    uint32_t a;
    asm("{ .reg .u64 t; cvta.to.shared.u64 t, %1; cvt.u32.u64 %0, t; }"
        : "=r"(a) : "l"(p));
    return a;
}
__device__ __forceinline__ uint32_t sw128(uint32_t o) {  // SW128 swizzle, 128B rows
    return o ^ ((o >> 3) & 0x70);
}
__device__ __forceinline__ void cp16(uint32_t dst, const void* src) {
    asm volatile("cp.async.cg.shared.global [%0], [%1], 16;" :: "r"(dst), "l"(src));
}
#define CP_COMMIT() asm volatile("cp.async.commit_group;" ::: "memory")
#define CP_WAIT(n)  asm volatile("cp.async.wait_group %0;" :: "n"(n) : "memory")

#define LDSM4(r, a) \
    asm volatile("ldmatrix.sync.aligned.m8n8.x4.shared.b16 {%0,%1,%2,%3}, [%4];" \
        : "=r"((r)[0]), "=r"((r)[1]), "=r"((r)[2]), "=r"((r)[3]) : "r"(a))

#define MMAF16(d, a, b0, b1) \
    asm volatile("mma.sync.aligned.m16n8k16.row.col.f32.f16.f16.f32 " \
        "{%0,%1,%2,%3}, {%4,%5,%6,%7}, {%8,%9}, {%0,%1,%2,%3};" \
        : "+f"((d)[0]), "+f"((d)[1]), "+f"((d)[2]), "+f"((d)[3]) \
        : "r"((a)[0]), "r"((a)[1]), "r"((a)[2]), "r"((a)[3]), "r"(b0), "r"(b1))

// forced 16B non-coherent load
#define LDG16(v, ptr) \
    asm volatile("ld.global.nc.v4.u32 {%0,%1,%2,%3}, [%4];" \
        : "=r"((v).x), "=r"((v).y), "=r"((v).z), "=r"((v).w) : "l"(ptr))

// ======================= mma.sync GEMM (fp16, 2-pass, BK=64) ===============
// D(4096 x 1024, fp16) = X(4096 x Kin) @ W(1024 x Kin)^T + bias
// CTA tile 128x128, BK=64, 8 warps (warp tile 32x64), cp.async double buffer.
// smem per stage (48KB): A | Bh | Bl, each 128 rows x 128B, SW128.
#define ARR_BYTES (128 * 128)               // 16384
#define STG_BYTES (3 * ARR_BYTES)           // 49152
#define GEMM_SMEM (2 * STG_BYTES)           // 98304

__global__ __launch_bounds__(256) void gemm_mma(
    const __half* __restrict__ A,
    const __half* __restrict__ Bh, const __half* __restrict__ Bl,
    const float* __restrict__ bias,
    __half* __restrict__ C,     // ldc = 1024, fp16
    int Kin)
{
    extern __shared__ char smem[];
    const uint32_t sb  = smem_u32(smem);
    const int tid  = threadIdx.x;
    const int lane = tid & 31;
    const int wid  = tid >> 5;
    const int bm   = blockIdx.y * 128;
    const int bn   = blockIdx.x * 128;
    const int m0   = (wid & 3) * 32;     // warp m-offset in tile
    const int n0   = (wid >> 2) * 64;    // warp n-offset in tile

    // cp.async chunk mapping: 128 rows x 8 segs(16B) per array = 1024 chunks,
    // 4 per thread (rows rc, rc+32, rc+64, rc+96)
    const int rc = tid >> 3;             // 0..31
    const int sc = tid & 7;              // 0..7

    const __half* gsrc[3] = { A, Bh, Bl };
    const int grow0[3] = { bm, bn, bn };

    uint32_t soff[3][4];
    #pragma unroll
    for (int a = 0; a < 3; a++)
        #pragma unroll
        for (int it = 0; it < 4; it++)
            soff[a][it] = a * ARR_BYTES +
                sw128((uint32_t)((rc + 32 * it) * 128 + sc * 16));

    const int nk = Kin / 64;

    // ---- issue stage 0 ----
    {
        const uint32_t bufb = sb;
        #pragma unroll
        for (int a = 0; a < 3; a++)
            #pragma unroll
            for (int it = 0; it < 4; it++)
                cp16(bufb + soff[a][it],
                     gsrc[a] + (size_t)(grow0[a] + rc + 32 * it) * Kin + sc * 8);
        CP_COMMIT();
    }

    float acc[2][8][4];
    #pragma unroll
    for (int i = 0; i < 2; i++)
        #pragma unroll
        for (int j = 0; j < 8; j++)
            #pragma unroll
            for (int q = 0; q < 4; q++)
                acc[i][j][q] = 0.0f;

    // ldmatrix per-lane address components
    const int a_row = lane & 15;
    const int a_kh  = (lane >> 4) & 1;
    const int b_row = ((lane >> 4) << 3) + (lane & 7);
    const int b_kh  = (lane >> 3) & 1;

    for (int s = 0; s < nk; s++) {
        const uint32_t bufb = sb + (uint32_t)(s & 1) * STG_BYTES;

        if (s + 1 < nk) {
            const uint32_t nb = sb + (uint32_t)((s + 1) & 1) * STG_BYTES;
            const int kb = (s + 1) * 64;
            #pragma unroll
            for (int a = 0; a < 3; a++)
                #pragma unroll
                for (int it = 0; it < 4; it++)
                    cp16(nb + soff[a][it],
                         gsrc[a] + (size_t)(grow0[a] + rc + 32 * it) * Kin + kb + sc * 8);
            CP_COMMIT();
            CP_WAIT(1);
        } else {
            CP_WAIT(0);
        }
        __syncthreads();

        #pragma unroll
        for (int kk = 0; kk < 4; kk++) {
            uint32_t fa[2][4];
            #pragma unroll
            for (int mt = 0; mt < 2; mt++) {
                const uint32_t off =
                    sw128((uint32_t)((m0 + mt * 16 + a_row) * 128 + kk * 32 + a_kh * 16));
                LDSM4(fa[mt], bufb + 0 * ARR_BYTES + off);
            }
            uint32_t fbh[4][4], fbl[4][4];
            #pragma unroll
            for (int nt = 0; nt < 4; nt++) {
                const uint32_t off =
                    sw128((uint32_t)((n0 + nt * 16 + b_row) * 128 + kk * 32 + b_kh * 16));
                LDSM4(fbh[nt], bufb + 1 * ARR_BYTES + off);
                LDSM4(fbl[nt], bufb + 2 * ARR_BYTES + off);
            }
            #pragma unroll
            for (int mt = 0; mt < 2; mt++) {
                #pragma unroll
                for (int ni = 0; ni < 8; ni++) {
                    const uint32_t bh0 = fbh[ni >> 1][(ni & 1) * 2];
                    const uint32_t bh1 = fbh[ni >> 1][(ni & 1) * 2 + 1];
                    const uint32_t bl0 = fbl[ni >> 1][(ni & 1) * 2];
                    const uint32_t bl1 = fbl[ni >> 1][(ni & 1) * 2 + 1];
                    MMAF16(acc[mt][ni], fa[mt], bh0, bh1);
                    MMAF16(acc[mt][ni], fa[mt], bl0, bl1);
                }
            }
        }
        __syncthreads();
    }

    // ---- epilogue: write D (fp16) with bias ----
    #pragma unroll
    for (int mt = 0; mt < 2; mt++) {
        const int r = bm + m0 + mt * 16 + (lane >> 2);
        #pragma unroll
        for (int ni = 0; ni < 8; ni++) {
            const int col = bn + n0 + ni * 8 + (lane & 3) * 2;
            const float b0 = bias[col], b1 = bias[col + 1];
            __half2 v0 = __floats2half2_rn(acc[mt][ni][0] + b0, acc[mt][ni][1] + b1);
            __half2 v1 = __floats2half2_rn(acc[mt][ni][2] + b0, acc[mt][ni][3] + b1);
            *(__half2*)(C + (size_t)r * 1024 + col)       = v0;
            *(__half2*)(C + (size_t)(r + 8) * 1024 + col) = v1;
        }
    }
}

// ======================= fused prologue: prep_w3 + geo in ONE kernel =======
// Blocks [0, 3072): weight prep (layer = bid/1024, chunk = bid%1024).
// Blocks [3072, 3328): geo MLP for 16 nodes each (256 threads; compute on
// tid<128, smem loads + pooled copy use all 256).
#define GEO_NODES 16
#define GEO_W2T   0
#define GEO_W1    (128 * 129)
#define GEO_B1    (GEO_W1 + 896)
#define GEO_B2    (GEO_B1 + 128)
#define GEO_ROI   (GEO_B2 + 128)
#define GEO_H     (GEO_ROI + 128)
#define GEO_SMEMF (GEO_H + GEO_NODES * 132)
#define GEO_SMEM  (GEO_SMEMF * 4)
#define PREP_BLOCKS 3072
#define GEO_BLOCKS  (NNODES / GEO_NODES)   // 256

__global__ __launch_bounds__(256) void pre_all(
    const float* __restrict__ rois,
    const float* __restrict__ pooled,
    const float* __restrict__ gW1, const float* __restrict__ gb1,
    const float* __restrict__ gW2, const float* __restrict__ gb2,
    const float* __restrict__ W0, const float* __restrict__ b0,
    const float* __restrict__ W1, const float* __restrict__ b1,
    const float* __restrict__ W2, const float* __restrict__ b2,
    __half* __restrict__ Wh, __half* __restrict__ Wl,
    float* __restrict__ biasL,
    float* __restrict__ out,
    __half* __restrict__ X0h)
{
    const int tid = threadIdx.x;

    if (blockIdx.x < PREP_BLOCKS) {
        // ---------------- weight prep ----------------
        const int layer = blockIdx.x >> 10;            // /1024
        const int blk   = blockIdx.x & 1023;
        const float* W = (layer == 0) ? W0 : (layer == 1) ? W1 : W2;
        const float* b = (layer == 0) ? b0 : (layer == 1) ? b1 : b2;
        const int Kin  = (layer == 0) ? INDIM : LDIM;

        __half* wh = Wh + (size_t)layer * WSTRIDE;
        __half* wl = Wl + (size_t)layer * WSTRIDE;

        int idx = blk * 256 + tid;
        if (idx < 512 * Kin) {
            int r = idx / Kin, c = idx % Kin;
            float vl = W[(size_t)r * 2 * Kin + c];
            float vr = W[(size_t)r * 2 * Kin + Kin + c];
            float d  = vr - vl;

            __half h = __float2half_rn(vl);
            wh[(size_t)r * Kin + c] = h;
            wl[(size_t)r * Kin + c] = __float2half_rn(vl - __half2float(h));
            h = __float2half_rn(d);
            wh[(size_t)(512 + r) * Kin + c] = h;
            wl[(size_t)(512 + r) * Kin + c] = __float2half_rn(d - __half2float(h));
        }
        if (idx < 512) {
            biasL[layer * 1024 + idx]       = 0.0f;
            biasL[layer * 1024 + 512 + idx] = b[idx];
        }
        return;
    }

    // ---------------- geo MLP + pooled copy ----------------
    extern __shared__ float s[];
    const int n0 = (blockIdx.x - PREP_BLOCKS) * GEO_NODES;

    for (int i = tid; i < 128 * 128; i += 256) {
        int r = i >> 7, c = i & 127;
        s[GEO_W2T + c * 129 + r] = gW2[i];
    }
    for (int i = tid; i < 896; i += 256) s[GEO_W1 + i] = gW1[i];
    if (tid < 128) {
        s[GEO_B1 + tid] = gb1[tid];
        s[GEO_B2 + tid] = gb2[tid];
    }
    if (tid < GEO_NODES * 7) {
        int node = tid / 7, j = tid - node * 7;
        s[GEO_ROI + node * 8 + j] = rois[(size_t)(n0 + node) * 7 + j];
    }
    __syncthreads();

    if (tid < 128) {
        #pragma unroll
        for (int node = 0; node < GEO_NODES; node++) {
            float a = s[GEO_B1 + tid];
            #pragma unroll
            for (int j = 0; j < 7; j++)
                a = fmaf(s[GEO_W1 + tid * 7 + j], s[GEO_ROI + node * 8 + j], a);
            s[GEO_H + node * 132 + tid] = fmaxf(a, 0.0f);
        }
    }
    __syncthreads();

    if (tid < 128) {
        float acc[GEO_NODES];
        #pragma unroll
        for (int node = 0; node < GEO_NODES; node++) acc[node] = s[GEO_B2 + tid];

        #pragma unroll 8
        for (int j = 0; j < 128; j += 4) {
            const float w0 = s[GEO_W2T + (j + 0) * 129 + tid];
            const float w1 = s[GEO_W2T + (j + 1) * 129 + tid];
            const float w2 = s[GEO_W2T + (j + 2) * 129 + tid];
            const float w3 = s[GEO_W2T + (j + 3) * 129 + tid];
            #pragma unroll
            for (int node = 0; node < GEO_NODES; node++) {
                float4 h = *(const float4*)&s[GEO_H + node * 132 + j];
                float a = acc[node];
                a = fmaf(w0, h.x, a);
                a = fmaf(w1, h.y, a);
                a = fmaf(w2, h.z, a);
                a = fmaf(w3, h.w, a);
                acc[node] = a;
            }
        }

        #pragma unroll
        for (int node = 0; node < GEO_NODES; node++) {
            const int n = n0 + node;
            const float g = fmaxf(acc[node], 0.0f);
            out[(size_t)n * OUTLD + CPOOL + tid] = g;
            X0h[(size_t)n * INDIM + CPOOL + tid] = __float2half_rn(g);
        }
    }

    // pooled copy: all 256 threads, 1 column each per node
    #pragma unroll
    for (int node = 0; node < GEO_NODES; node++) {
        const int n = n0 + node;
        const float v = pooled[(size_t)n * CPOOL + tid];
        out[(size_t)n * OUTLD + tid] = v;
        X0h[(size_t)n * INDIM + tid] = __float2half_rn(v);
    }
}

// ---------------- aggregation: fp16 hmax reduction ------------------------
__global__ __launch_bounds__(256) void aggregate(
    const __half* __restrict__ D,
    const int*   __restrict__ src,
    __half* __restrict__ Xh,         // 4096 x 512
    float* __restrict__ out,         // 4096 x 1920
    int out_off, int write_xh)
{
    const int n   = blockIdx.x * 4 + (threadIdx.x >> 6);
    const int l64 = threadIdx.x & 63;      // 0..63, owns 8 halves

    const int* sp = src + n * KNBR;
    const size_t coff = (size_t)l64 * 8;

    __half2 M0, M1, M2, M3;
    {
        uint4 w0, w1, w2, w3;
        LDG16(w0, D + (size_t)sp[0] * 1024 + coff);
        LDG16(w1, D + (size_t)sp[1] * 1024 + coff);
        LDG16(w2, D + (size_t)sp[2] * 1024 + coff);
        LDG16(w3, D + (size_t)sp[3] * 1024 + coff);
        M0 = *(__half2*)&w0.x;  M1 = *(__half2*)&w0.y;
        M2 = *(__half2*)&w0.z;  M3 = *(__half2*)&w0.w;
        M0 = __hmax2(M0, *(__half2*)&w1.x); M1 = __hmax2(M1, *(__half2*)&w1.y);
        M2 = __hmax2(M2, *(__half2*)&w1.z); M3 = __hmax2(M3, *(__half2*)&w1.w);
        M0 = __hmax2(M0, *(__half2*)&w2.x); M1 = __hmax2(M1, *(__half2*)&w2.y);
        M2 = __hmax2(M2, *(__half2*)&w2.z); M3 = __hmax2(M3, *(__half2*)&w2.w);
        M0 = __hmax2(M0, *(__half2*)&w3.x); M1 = __hmax2(M1, *(__half2*)&w3.y);
        M2 = __hmax2(M2, *(__half2*)&w3.z); M3 = __hmax2(M3, *(__half2*)&w3.w);
    }
    #pragma unroll
    for (int k0 = 4; k0 < KNBR; k0 += 4) {
        uint4 w0, w1, w2, w3;
        LDG16(w0, D + (size_t)sp[k0 + 0] * 1024 + coff);
        LDG16(w1, D + (size_t)sp[k0 + 1] * 1024 + coff);
        LDG16(w2, D + (size_t)sp[k0 + 2] * 1024 + coff);
        LDG16(w3, D + (size_t)sp[k0 + 3] * 1024 + coff);
        M0 = __hmax2(M0, *(__half2*)&w0.x); M1 = __hmax2(M1, *(__half2*)&w0.y);
        M2 = __hmax2(M2, *(__half2*)&w0.z); M3 = __hmax2(M3, *(__half2*)&w0.w);
        M0 = __hmax2(M0, *(__half2*)&w1.x); M1 = __hmax2(M1, *(__half2*)&w1.y);
        M2 = __hmax2(M2, *(__half2*)&w1.z); M3 = __hmax2(M3, *(__half2*)&w1.w);
        M0 = __hmax2(M0, *(__half2*)&w2.x); M1 = __hmax2(M1, *(__half2*)&w2.y);
        M2 = __hmax2(M2, *(__half2*)&w2.z); M3 = __hmax2(M3, *(__half2*)&w2.w);
        M0 = __hmax2(M0, *(__half2*)&w3.x); M1 = __hmax2(M1, *(__half2*)&w3.y);
        M2 = __hmax2(M2, *(__half2*)&w3.z); M3 = __hmax2(M3, *(__half2*)&w3.w);
    }

    uint4 cw = *(const uint4*)(D + (size_t)n * 1024 + 512 + coff);
    float2 c0 = __half22float2(*(__half2*)&cw.x);
    float2 c1 = __half22float2(*(__half2*)&cw.y);
    float2 c2 = __half22float2(*(__half2*)&cw.z);
    float2 c3 = __half22float2(*(__half2*)&cw.w);
    float2 m0 = __half22float2(M0);
    float2 m1 = __half22float2(M1);
    float2 m2 = __half22float2(M2);
    float2 m3 = __half22float2(M3);

    float4 r0, r1;
    r0.x = fmaxf(m0.x + c0.x, 0.0f);  r0.y = fmaxf(m0.y + c0.y, 0.0f);
    r0.z = fmaxf(m1.x + c1.x, 0.0f);  r0.w = fmaxf(m1.y + c1.y, 0.0f);
    r1.x = fmaxf(m2.x + c2.x, 0.0f);  r1.y = fmaxf(m2.y + c2.y, 0.0f);
    r1.z = fmaxf(m3.x + c3.x, 0.0f);  r1.w = fmaxf(m3.y + c3.y, 0.0f);

    float* op = out + (size_t)n * OUTLD + out_off + l64 * 8;
    *(float4*)(op)     = r0;
    *(float4*)(op + 4) = r1;

    if (write_xh) {
        uint4 hx;
        *(__half2*)&hx.x = __floats2half2_rn(r0.x, r0.y);
        *(__half2*)&hx.y = __floats2half2_rn(r0.z, r0.w);
        *(__half2*)&hx.z = __floats2half2_rn(r1.x, r1.y);
        *(__half2*)&hx.w = __floats2half2_rn(r1.z, r1.w);
        *(uint4*)(Xh + (size_t)n * LDIM + l64 * 8) = hx;
    }
}

// ---------------------------------------------------------------------------
extern "C" void kernel_launch(void* const* d_in, const int* in_sizes, int n_in,
                              void* d_out, int out_size)
{
    const float* rois   = (const float*)d_in[0];
    const float* pooled = (const float*)d_in[1];
    const int*   edge   = (const int*)  d_in[2];   // (2, 65536): row 0 = src
    const float* gW1    = (const float*)d_in[3];
    const float* gb1    = (const float*)d_in[4];
    const float* gW2    = (const float*)d_in[5];
    const float* gb2    = (const float*)d_in[6];
    const float* fcW[3] = {(const float*)d_in[7], (const float*)d_in[9],  (const float*)d_in[11]};
    const float* fcb[3] = {(const float*)d_in[8], (const float*)d_in[10], (const float*)d_in[12]};
    float* out = (float*)d_out;

    const int* src = edge;

    float *biasL;
    __half *D, *X0h, *Xh, *Wh, *Wl;
    cudaGetSymbolAddress((void**)&D,     g_D);
    cudaGetSymbolAddress((void**)&biasL, g_biasL);
    cudaGetSymbolAddress((void**)&X0h,   g_X0h);
    cudaGetSymbolAddress((void**)&Xh,    g_Xh);
    cudaGetSymbolAddress((void**)&Wh,    g_Wh);
    cudaGetSymbolAddress((void**)&Wl,    g_Wl);

    cudaFuncSetAttribute(gemm_mma, cudaFuncAttributeMaxDynamicSharedMemorySize, GEMM_SMEM);
    cudaFuncSetAttribute(pre_all,  cudaFuncAttributeMaxDynamicSharedMemorySize, GEO_SMEM);

    // 1) fused prologue: weight prep + geo MLP + pooled copy, one launch
    pre_all<<<PREP_BLOCKS + GEO_BLOCKS, 256, GEO_SMEM>>>(
        rois, pooled, gW1, gb1, gW2, gb2,
        fcW[0], fcb[0], fcW[1], fcb[1], fcW[2], fcb[2],
        Wh, Wl, biasL, out, X0h);

    // 2) three EdgeConv layers
    const int Kin[3]    = {INDIM, LDIM, LDIM};
    const int outOff[3] = {384, 384 + 512, 384 + 1024};

    for (int l = 0; l < 3; l++) {
        const __half* Ain = (l == 0) ? X0h : Xh;
        gemm_mma<<<dim3(1024 / 128, NNODES / 128), 256, GEMM_SMEM>>>(
            Ain, Wh + (size_t)l * WSTRIDE, Wl + (size_t)l * WSTRIDE,
            biasL + l * 1024, D, Kin[l]);

        aggregate<<<NNODES / 4, 256>>>(D, src, Xh, out, outOff[l], l < 2 ? 1 : 0);
    }
}